// round 1
// baseline (speedup 1.0000x reference)
#include <cuda_runtime.h>

// DigitCaps dynamic routing, fully fused, one block per batch element.
//
// Key identity: u_hat only ever appears inside bilinear contractions, so it is
// never materialized:
//   logits:  b[n,o]   = sum_q x[n,q] * WV[c,o,q],  WV[c,o,q] = sum_p W[c,o,p,q]*v[o,p]
//   sums:    s[o,p]   = sum_{c,q} W[c,o,p,q] * y[c,o,q],
//            y[c,o,q] = sum_hw softmax_o(b)[c,hw,o] * x[c,hw,q]
//   b_ij accumulation is linear in v, so pass k uses vsum = v0+..+v_{k-1}.
//   iter 0: c_ij == 0.1 exactly -> s0 = 0.1 * sum_{c,q} W[c,o,p,q]*xsum[c,q].

#define C_   32
#define HW_  144
#define Q_   8
#define O_   10
#define P_   16
#define NT   384      // 32 c-lanes x 12 hw-group warps

// shared memory layout (floats)
#define OFF_WV   0                       // WV transposed: [(o*8+q)*32 + c]   (2560)
#define OFF_Y    2560                    // y: [c*80 + o*8 + q]               (2560)
#define OFF_PART 5120                    // per-thread y partials [NT][81]
#define PART_ROW 81                      // 81*4B: 17*c mod 32 -> conflict-free
#define OFF_S    (5120 + NT*PART_ROW)    // 36224: s partials [2][160]
#define OFF_VS   (OFF_S + 320)           // 36544: vsum accumulator [160]
#define SMEM_FLOATS (OFF_VS + 160)       // 36704 floats = 146816 B

__device__ __forceinline__ void s_and_squash(float* sm, const float* __restrict__ W,
                                             bool accum_vs, float* __restrict__ outp, int t)
{
    // s[o,p] = sum_{c,q} W[c,o,p,q] * y[c,o,q]; split c-range over 2 halves.
    if (t < 320) {
        const int half = t / 160;
        const int r    = t - half * 160;
        const int o    = r >> 4;
        const int p    = r & 15;
        float acc = 0.f;
        #pragma unroll
        for (int ci = 0; ci < 16; ++ci) {
            const int cc = half * 16 + ci;
            const float* wrow = W + ((size_t)(cc * O_ + o) * P_ + p) * Q_;
            const float4 wa = *reinterpret_cast<const float4*>(wrow);
            const float4 wb = *reinterpret_cast<const float4*>(wrow + 4);
            const float* y = sm + OFF_Y + cc * 80 + o * 8;  // broadcast across p-lanes
            acc = fmaf(wa.x, y[0], acc); acc = fmaf(wa.y, y[1], acc);
            acc = fmaf(wa.z, y[2], acc); acc = fmaf(wa.w, y[3], acc);
            acc = fmaf(wb.x, y[4], acc); acc = fmaf(wb.y, y[5], acc);
            acc = fmaf(wb.z, y[6], acc); acc = fmaf(wb.w, y[7], acc);
        }
        sm[OFF_S + half * 160 + r] = acc;
    }
    __syncthreads();
    if (t < 160) {   // 5 full warps; lanes 0..15 / 16..31 are two different o's
        const float s = sm[OFF_S + t] + sm[OFF_S + 160 + t];
        float sq = s * s;
        sq += __shfl_xor_sync(0xffffffffu, sq, 1);
        sq += __shfl_xor_sync(0xffffffffu, sq, 2);
        sq += __shfl_xor_sync(0xffffffffu, sq, 4);
        sq += __shfl_xor_sync(0xffffffffu, sq, 8);
        const float v = s * sqrtf(sq) / (1.f + sq);   // sn*s/((1+sn)*sqrt(sn))
        if (accum_vs) sm[OFF_VS + t] += v;
        if (outp)     outp[t] = v;
    }
    __syncthreads();
}

__device__ __forceinline__ void routing_pass(float* sm, const float* __restrict__ xb,
                                             const float* __restrict__ W,
                                             int t, int c, int g)
{
    // WV[c,o,q] = sum_p W[c,o,p,q] * vsum[o,p]  (stored transposed [o][q][c])
    if (t < 320) {
        const int c2 = t & 31;
        const int o  = t >> 5;
        const float* wrow = W + (size_t)(c2 * O_ + o) * P_ * Q_;
        float wv[8];
        #pragma unroll
        for (int q = 0; q < 8; ++q) wv[q] = 0.f;
        #pragma unroll
        for (int p = 0; p < 16; ++p) {
            const float vv = sm[OFF_VS + o * 16 + p];     // warp-broadcast
            const float4 wa = *reinterpret_cast<const float4*>(wrow + p * 8);
            const float4 wb = *reinterpret_cast<const float4*>(wrow + p * 8 + 4);
            wv[0] = fmaf(wa.x, vv, wv[0]); wv[1] = fmaf(wa.y, vv, wv[1]);
            wv[2] = fmaf(wa.z, vv, wv[2]); wv[3] = fmaf(wa.w, vv, wv[3]);
            wv[4] = fmaf(wb.x, vv, wv[4]); wv[5] = fmaf(wb.y, vv, wv[5]);
            wv[6] = fmaf(wb.z, vv, wv[6]); wv[7] = fmaf(wb.w, vv, wv[7]);
        }
        #pragma unroll
        for (int q = 0; q < 8; ++q) sm[OFF_WV + (o * 8 + q) * 32 + c2] = wv[q];
    }
    __syncthreads();

    // main loop: per (c, hw): logits -> local softmax -> accumulate y in regs
    float yacc[80];
    #pragma unroll
    for (int k = 0; k < 80; ++k) yacc[k] = 0.f;

    for (int i = 0; i < 12; ++i) {
        const int hw = g * 12 + i;
        const float4 xa = *reinterpret_cast<const float4*>(xb + hw * 8);
        const float4 xc = *reinterpret_cast<const float4*>(xb + hw * 8 + 4);
        const float xq[8] = {xa.x, xa.y, xa.z, xa.w, xc.x, xc.y, xc.z, xc.w};
        float bl[10];
        #pragma unroll
        for (int o = 0; o < 10; ++o) {
            float acc = 0.f;
            #pragma unroll
            for (int q = 0; q < 8; ++q)
                acc = fmaf(sm[OFF_WV + (o * 8 + q) * 32 + c], xq[q], acc);
            bl[o] = acc;
        }
        float M = bl[0];
        #pragma unroll
        for (int o = 1; o < 10; ++o) M = fmaxf(M, bl[o]);
        float Z = 0.f;
        #pragma unroll
        for (int o = 0; o < 10; ++o) { bl[o] = __expf(bl[o] - M); Z += bl[o]; }
        const float rz = 1.f / Z;
        #pragma unroll
        for (int o = 0; o < 10; ++o) {
            const float cij = bl[o] * rz;
            #pragma unroll
            for (int q = 0; q < 8; ++q)
                yacc[o * 8 + q] = fmaf(cij, xq[q], yacc[o * 8 + q]);
        }
    }

    // reduce y over the 12 hw-group warps via smem
    #pragma unroll
    for (int k = 0; k < 80; ++k) sm[OFF_PART + t * PART_ROW + k] = yacc[k];
    __syncthreads();
    if (t < 320) {
        const int c2 = t & 31;
        const int o  = t >> 5;
        #pragma unroll
        for (int q = 0; q < 8; ++q) {
            float acc = 0.f;
            #pragma unroll
            for (int gg = 0; gg < 12; ++gg)
                acc += sm[OFF_PART + (gg * 32 + c2) * PART_ROW + o * 8 + q];
            sm[OFF_Y + c2 * 80 + o * 8 + q] = acc;
        }
    }
    __syncthreads();
}

__global__ __launch_bounds__(NT, 1)
void digitcaps_kernel(const float* __restrict__ x, const float* __restrict__ W,
                      float* __restrict__ out)
{
    extern __shared__ float sm[];
    const int t = threadIdx.x;
    const int b = blockIdx.x;
    const int c = t & 31;   // lane = input channel
    const int g = t >> 5;   // warp = hw group
    const float* xb = x + ((size_t)b * C_ + c) * HW_ * Q_;

    // ---- pass 0: c_ij = 0.1 exactly -> y[c,o,q] = 0.1 * sum_hw x[c,hw,q]
    if (t < 256) {
        const int c2 = t >> 3, q = t & 7;
        const float* p = x + ((size_t)b * C_ + c2) * HW_ * Q_ + q;
        float a0 = 0.f, a1 = 0.f, a2 = 0.f, a3 = 0.f;
        #pragma unroll
        for (int hw = 0; hw < HW_; hw += 4) {
            a0 += p[(hw + 0) * 8];
            a1 += p[(hw + 1) * 8];
            a2 += p[(hw + 2) * 8];
            a3 += p[(hw + 3) * 8];
        }
        const float acc = ((a0 + a1) + (a2 + a3)) * 0.1f;
        #pragma unroll
        for (int o = 0; o < 10; ++o) sm[OFF_Y + c2 * 80 + o * 8 + q] = acc;
    }
    if (t < 160) sm[OFF_VS + t] = 0.f;
    __syncthreads();
    s_and_squash(sm, W, true, nullptr, t);          // vsum = v0

    // ---- pass 1: logits use v0
    routing_pass(sm, xb, W, t, c, g);
    s_and_squash(sm, W, true, nullptr, t);          // vsum = v0 + v1

    // ---- pass 2: logits use v0+v1; squash -> output
    routing_pass(sm, xb, W, t, c, g);
    s_and_squash(sm, W, false, out + (size_t)b * 160, t);
}

extern "C" void kernel_launch(void* const* d_in, const int* in_sizes, int n_in,
                              void* d_out, int out_size)
{
    (void)in_sizes; (void)n_in; (void)out_size;
    const float* x = (const float*)d_in[0];
    const float* W = (const float*)d_in[1];
    float* out = (float*)d_out;

    const int smem_bytes = SMEM_FLOATS * (int)sizeof(float);  // ~147 KB
    cudaFuncSetAttribute(digitcaps_kernel,
                         cudaFuncAttributeMaxDynamicSharedMemorySize, smem_bytes);
    digitcaps_kernel<<<128, NT, smem_bytes>>>(x, W, out);
}